// round 13
// baseline (speedup 1.0000x reference)
#include <cuda_runtime.h>
#include <cuda_bf16.h>
#include <cstdint>

#define BB   4
#define SQ   2048
#define DM   1024
#define NH   16
#define HD   64
#define BS   (BB*SQ)      // 8192
#define N3   (3*DM)       // 3072

typedef unsigned long long u64;
typedef unsigned int u32;
typedef __nv_bfloat16 bf16;
typedef __nv_bfloat162 bf162;

// Q pre-scale: 1/sqrt(64) * log2(e)  (softmax done in base-2 domain)
#define QSCALE 0.1803368801111204f

// ---------------- scratch (device globals; no allocation allowed) -----------
__device__ __align__(16) bf16 g_qhi[(size_t)BB*NH*SQ*HD];
__device__ __align__(16) bf16 g_qlo[(size_t)BB*NH*SQ*HD];
__device__ __align__(16) bf16 g_khi[(size_t)BB*NH*SQ*HD];
__device__ __align__(16) bf16 g_klo[(size_t)BB*NH*SQ*HD];
__device__ __align__(16) bf16 g_vhi[(size_t)BB*NH*SQ*HD];
__device__ __align__(16) bf16 g_vlo[(size_t)BB*NH*SQ*HD];

__device__ __align__(16) float g_xtf[(size_t)BS*DM];   // x, tf32-rounded
__device__ __align__(16) float g_atf[(size_t)BS*DM];   // attn out, tf32-rounded
// weights stored PERMUTED fragment-ready: [nb][kc][4096 floats]
__device__ __align__(16) float g_wq[(size_t)N3*DM];
__device__ __align__(16) float g_wp[(size_t)DM*DM];

// ---------------- helpers -----------------------------------------------------
__device__ __forceinline__ void cp_async16(u32 smem, const void* g) {
    asm volatile("cp.async.cg.shared.global [%0], [%1], 16;" :: "r"(smem), "l"(g));
}
__device__ __forceinline__ void cp_commit()  { asm volatile("cp.async.commit_group;"); }
__device__ __forceinline__ void cp_wait0()   { asm volatile("cp.async.wait_group 0;"); }
__device__ __forceinline__ void cp_wait1()   { asm volatile("cp.async.wait_group 1;"); }
__device__ __forceinline__ u32 smem_u32(const void* p) {
    return (u32)__cvta_generic_to_shared(p);
}
__device__ __forceinline__ float ex2(float x) {
    float y; asm("ex2.approx.f32 %0, %1;" : "=f"(y) : "f"(x)); return y;
}
__device__ __forceinline__ float tf32r(float x) {
    float y; asm("cvt.rna.tf32.f32 %0, %1;" : "=f"(y) : "f"(x)); return y;
}
__device__ __forceinline__ void ldsm4(u32& r0, u32& r1, u32& r2, u32& r3, u32 a) {
    asm volatile("ldmatrix.sync.aligned.m8n8.x4.shared.b16 {%0,%1,%2,%3}, [%4];"
                 : "=r"(r0), "=r"(r1), "=r"(r2), "=r"(r3) : "r"(a));
}
__device__ __forceinline__ void ldsm4t(u32& r0, u32& r1, u32& r2, u32& r3, u32 a) {
    asm volatile("ldmatrix.sync.aligned.m8n8.x4.trans.shared.b16 {%0,%1,%2,%3}, [%4];"
                 : "=r"(r0), "=r"(r1), "=r"(r2), "=r"(r3) : "r"(a));
}
__device__ __forceinline__ void mma16816(float* d, const u32* a, const u32* b) {
    asm volatile(
        "mma.sync.aligned.m16n8k16.row.col.f32.bf16.bf16.f32 "
        "{%0,%1,%2,%3}, {%4,%5,%6,%7}, {%8,%9}, {%0,%1,%2,%3};"
        : "+f"(d[0]), "+f"(d[1]), "+f"(d[2]), "+f"(d[3])
        : "r"(a[0]), "r"(a[1]), "r"(a[2]), "r"(a[3]), "r"(b[0]), "r"(b[1]));
}
__device__ __forceinline__ void mma_tf32(float* d, const u32* a, const u32* b) {
    asm volatile(
        "mma.sync.aligned.m16n8k8.row.col.f32.tf32.tf32.f32 "
        "{%0,%1,%2,%3}, {%4,%5,%6,%7}, {%8,%9}, {%0,%1,%2,%3};"
        : "+f"(d[0]), "+f"(d[1]), "+f"(d[2]), "+f"(d[3])
        : "r"(a[0]), "r"(a[1]), "r"(a[2]), "r"(a[3]), "r"(b[0]), "r"(b[1]));
}
__device__ __forceinline__ u32 pkbf(float lo, float hi) {
    bf162 t = __halves2bfloat162(__float2bfloat16(lo), __float2bfloat16(hi));
    return *(u32*)&t;
}
// pack upper bf16 halves of two fp32 (RZ split): low16 = a>>16, high16 = b>>16
__device__ __forceinline__ u32 prmt_hi2(u32 a, u32 b) {
    u32 d; asm("prmt.b32 %0, %1, %2, 0x7632;" : "=r"(d) : "r"(a), "r"(b));
    return d;
}
// swizzled byte offset in a [rows x 128B] tile (SW128 style)
__device__ __forceinline__ u32 swz(int r, int c) {
    return (u32)(r * 128 + ((c ^ (r & 7)) * 16));
}

// ============================================================================
// Merged prep kernel: x tf32-round + both weight transposes into PERMUTED
// fragment-ready layout. blocks [0,8192): x  [8192,11264): attw  [11264,12288): pw
// Permuted layout: float index = (nb*(K/32)+kc)*4096 + nn*32 + (ks^(nn&3))*8
//                                + b_lk*2 + hi
// where n = nb*128+nn, k = kc*32 + ks*8 + (hi*4 + b_lk).
// ============================================================================
__global__ __launch_bounds__(256) void conv_all(const float* __restrict__ x,
                                                const float* __restrict__ attw,
                                                const float* __restrict__ pw)
{
    __shared__ float t[32][33];
    const int bid = blockIdx.x;
    if (bid < 8192) {
        const int i = bid * 256 + threadIdx.x;      // n4 = 2097152
        float4 v = ((const float4*)x)[i];
        v.x = tf32r(v.x); v.y = tf32r(v.y); v.z = tf32r(v.z); v.w = tf32r(v.w);
        ((float4*)g_xtf)[i] = v;
        return;
    }
    const float* w; float* dst; int K, N, n0, k0;
    if (bid < 8192 + 3072) {
        const int tb = bid - 8192;
        w = attw; dst = g_wq; K = DM; N = N3;
        n0 = (tb % 96) * 32; k0 = (tb / 96) * 32;
    } else {
        const int tb = bid - 11264;
        w = pw; dst = g_wp; K = DM; N = DM;
        n0 = (tb % 32) * 32; k0 = (tb / 32) * 32;
    }
    const int xl = threadIdx.x & 31, y = (threadIdx.x >> 5) * 4;
#pragma unroll
    for (int r = 0; r < 4; ++r)
        t[y + r][xl] = w[(size_t)(k0 + y + r) * N + n0 + xl];
    __syncthreads();
#pragma unroll
    for (int r = 0; r < 4; ++r) {
        const int n = n0 + y + r, kk = k0 + xl;
        const int nb = n >> 7, nn = n & 127;
        const int kc = kk >> 5, k5 = kk & 31;
        const int ks = k5 >> 3, wv = k5 & 7;
        const int b_lk = wv & 3, hi = wv >> 2;
        const size_t idx = ((size_t)(nb * (K >> 5) + kc) << 12)
                         + (nn << 5) + ((ks ^ (nn & 3)) << 3) + (b_lk << 1) + hi;
        dst[idx] = tf32r(t[xl][y + r]);
    }
}

// ============================================================================
// TF32 single-pass GEMM via mma.sync.m16n8k8. 128x128 CTA, 8 warps (64x32),
// BK=32, 3 stages x 32KB = 96KB -> 2 CTAs/SM, 1 sync/chunk.
// B tiles are fragment-ready (linear cp.async, LDS.64 frag loads).
// MODE 0: qkv -> bf16 hi/lo scatter (Q scaled).  MODE 1: proj -> fp32 out.
// ============================================================================
template<int MODE>
__global__ __launch_bounds__(256, 2) void mma_gemm(const float* __restrict__ bias,
                                                   float* __restrict__ outp)
{
    extern __shared__ char smem[];
    const u32 sb = smem_u32(smem);
    const int tx = threadIdx.x, wid = tx >> 5, lane = tx & 31;
    const int m0 = blockIdx.y * 128, n0 = blockIdx.x * 128;
    const int K = DM;
    const int NCH = K / 32;                 // 32 chunks

    const float* Ag = MODE ? g_atf : g_xtf;
    const float* Bg = MODE ? g_wp  : g_wq;
    const float* Bblk = Bg + ((size_t)(n0 >> 7) * (K >> 5) << 12);

    const int wm = (wid & 1) * 64;
    const int wn = (wid >> 1) * 32;

    auto load_chunk = [&](int ci, int stage) {
        // A: 128 rows x 32 fp32, SW128-swizzled rows
        {
            const u32 tb = sb + (u32)(stage * 32768);
#pragma unroll
            for (int u = 0; u < 4; ++u) {
                const int id = tx + 256 * u;
                const int r = id >> 3, c = id & 7;
                cp_async16(tb + swz(r, c),
                           Ag + (size_t)(m0 + r) * K + ci * 32 + c * 4);
            }
        }
        // B: verbatim 16KB fragment-ready block
        {
            const u32 tb = sb + (u32)(stage * 32768 + 16384);
            const float* src = Bblk + ((size_t)ci << 12);
#pragma unroll
            for (int u = 0; u < 4; ++u) {
                const int id = tx + 256 * u;
                cp_async16(tb + id * 16, src + id * 4);
            }
        }
        cp_commit();
    };

    float acc[4][4][4];
#pragma unroll
    for (int mt = 0; mt < 4; ++mt)
#pragma unroll
        for (int nt = 0; nt < 4; ++nt)
#pragma unroll
            for (int e = 0; e < 4; ++e) acc[mt][nt][e] = 0.f;

    load_chunk(0, 0);
    load_chunk(1, 1);

    const int a_lrow = lane & 15;
    const int a_lc   = lane >> 4;
    const int b_q    = (lane >> 2) & 3;     // (bn & 3) component
    const int b_base = (wn + (lane >> 2)) * 32 + (lane & 3) * 2;

    for (int i = 0; i < NCH; ++i) {
        const int s = i % 3;
        if (i + 1 < NCH) cp_wait1(); else cp_wait0();
        __syncthreads();
        if (i + 2 < NCH) load_chunk(i + 2, (i + 2) % 3);

        const u32 tA = sb + (u32)(s * 32768);
        const float* pB = (const float*)(smem + s * 32768 + 16384);

#pragma unroll
        for (int ks = 0; ks < 4; ++ks) {
            u32 af[4][4];
#pragma unroll
            for (int mt = 0; mt < 4; ++mt) {
                const int row = wm + mt * 16 + a_lrow;
                ldsm4(af[mt][0], af[mt][1], af[mt][2], af[mt][3],
                      tA + swz(row, ks * 2 + a_lc));
            }
            u32 bfr[4][2];
            const int perm8 = (ks ^ b_q) << 3;
#pragma unroll
            for (int nt = 0; nt < 4; ++nt) {
                float2 bv = *(const float2*)(pB + b_base + nt * 256 + perm8);
                bfr[nt][0] = __float_as_uint(bv.x);
                bfr[nt][1] = __float_as_uint(bv.y);
            }
#pragma unroll
            for (int mt = 0; mt < 4; ++mt)
#pragma unroll
                for (int nt = 0; nt < 4; ++nt)
                    mma_tf32(acc[mt][nt], af[mt], bfr[nt]);
        }
    }

    const int r_in  = lane >> 2;
    const int cpair = (lane & 3) * 2;

    if (MODE == 0) {
        const int seg = n0 >> 10;
        bf16 *dhi, *dlo;
        if (seg == 0)      { dhi = g_qhi; dlo = g_qlo; }
        else if (seg == 1) { dhi = g_khi; dlo = g_klo; }
        else               { dhi = g_vhi; dlo = g_vlo; }
        const float qs = (seg == 0) ? QSCALE : 1.0f;
#pragma unroll
        for (int mt = 0; mt < 4; ++mt)
#pragma unroll
            for (int nt = 0; nt < 4; ++nt)
#pragma unroll
                for (int hh = 0; hh < 2; ++hh) {
                    const int m = m0 + wm + mt * 16 + r_in + hh * 8;
                    const int n = n0 + wn + nt * 8 + cpair;
                    const int b  = m >> 11;
                    const int sI = m & 2047;
                    const int nn = n & 1023;
                    const int h  = nn >> 6, dd = nn & 63;
                    const float vx = (acc[mt][nt][hh*2+0] + bias[n]) * qs;
                    const float vy = (acc[mt][nt][hh*2+1] + bias[n+1]) * qs;
                    const bf16 hx = __float2bfloat16(vx);
                    const bf16 hy = __float2bfloat16(vy);
                    const size_t idx = ((((size_t)b * NH + h) * SQ + sI) << 6) + dd;
                    *(bf162*)(dhi + idx) = __halves2bfloat162(hx, hy);
                    *(bf162*)(dlo + idx) = __halves2bfloat162(
                        __float2bfloat16(vx - __bfloat162float(hx)),
                        __float2bfloat16(vy - __bfloat162float(hy)));
                }
    } else {
#pragma unroll
        for (int mt = 0; mt < 4; ++mt)
#pragma unroll
            for (int nt = 0; nt < 4; ++nt)
#pragma unroll
                for (int hh = 0; hh < 2; ++hh) {
                    const int m = m0 + wm + mt * 16 + r_in + hh * 8;
                    const int n = n0 + wn + nt * 8 + cpair;
                    float2 v;
                    v.x = acc[mt][nt][hh * 2 + 0] + bias[n];
                    v.y = acc[mt][nt][hh * 2 + 1] + bias[n + 1];
                    *(float2*)(outp + (size_t)m * DM + n) = v;
                }
    }
}

// ============================================================================
// Tensor-core flash attention (bf16x3). CTA = 128 q-rows x one (b,h). 8 warps.
// K-chunks of 64 keys, 2 stages, 96KB -> 2 CTAs/SM. LPT long-tiles-first.
// P hi/lo via exact RZ bit-split (PRMT + sub), epilogue writes tf32 fp32.
// ============================================================================
__global__ __launch_bounds__(256, 2) void attn_mma()
{
    extern __shared__ char smem[];
    const u32 sb = smem_u32(smem);
    const int tx = threadIdx.x, wid = tx >> 5, lane = tx & 31;
    const int qt = (int)gridDim.x - 1 - (int)blockIdx.x;   // LPT
    const int bh = blockIdx.y;
    const int q0 = qt * 128;
    const int wm = wid * 16;
    const size_t base = (size_t)bh * SQ * HD;

    const bf16* Qh = g_qhi + base;
    const bf16* Ql = g_qlo + base;
    const bf16* Kh = g_khi + base;
    const bf16* Kl = g_klo + base;
    const bf16* Vh = g_vhi + base;
    const bf16* Vl = g_vlo + base;

#pragma unroll
    for (int u = 0; u < 4; ++u) {
        const int id = tx + 256 * u;
        const int r = id >> 3, c = id & 7;
        cp_async16(sb + swz(r, c),         Qh + (size_t)(q0 + r) * HD + c * 8);
        cp_async16(sb + 16384 + swz(r, c), Ql + (size_t)(q0 + r) * HD + c * 8);
    }
    auto load_chunk = [&](int kt, int s) {
        const int k0 = kt * 64;
        const u32 st = sb + 32768 + (u32)s * 32768;
#pragma unroll
        for (int u = 0; u < 2; ++u) {
            const int id = tx + 256 * u;
            const int r = id >> 3, c = id & 7;
            cp_async16(st + swz(r, c),          Kh + (size_t)(k0 + r) * HD + c * 8);
            cp_async16(st + 8192 + swz(r, c),   Kl + (size_t)(k0 + r) * HD + c * 8);
            cp_async16(st + 16384 + swz(r, c),  Vh + (size_t)(k0 + r) * HD + c * 8);
            cp_async16(st + 24576 + swz(r, c),  Vl + (size_t)(k0 + r) * HD + c * 8);
        }
        cp_commit();
    };
    load_chunk(0, 0);                 // group includes Q loads
    const int NCH = 2 * qt + 2;       // always >= 2
    load_chunk(1, 1);

    float O[8][4];
#pragma unroll
    for (int jn = 0; jn < 8; ++jn)
#pragma unroll
        for (int e = 0; e < 4; ++e) O[jn][e] = 0.f;
    float mrow[2] = {-1e30f, -1e30f};
    float lrow[2] = {0.f, 0.f};

    const int a_lrow = lane & 15;
    const int a_lc   = lane >> 4;
    const int b_lrow = lane & 7;
    const int b_lc   = (lane >> 3) & 1;
    const int b_sub  = (lane >> 4) & 1;

    for (int kt = 0; kt < NCH; ++kt) {
        const int s = kt & 1;
        const int k0 = kt * 64;
        if (kt + 1 < NCH) cp_wait1(); else cp_wait0();
        __syncthreads();

        const bool active = (k0 <= q0 + wm + 15);
        if (active) {
            const u32 stK  = sb + 32768 + (u32)s * 32768;
            const u32 stKl = stK + 8192;
            const u32 stV  = stK + 16384;
            const u32 stVl = stK + 24576;

            float S[8][4];
#pragma unroll
            for (int n = 0; n < 8; ++n)
#pragma unroll
                for (int e = 0; e < 4; ++e) S[n][e] = 0.f;

#pragma unroll
            for (int kt2 = 0; kt2 < 4; ++kt2) {
                u32 qh[4], ql[4];
                {
                    const u32 a = swz(wm + a_lrow, kt2 * 2 + a_lc);
                    ldsm4(qh[0], qh[1], qh[2], qh[3], sb + a);
                    ldsm4(ql[0], ql[1], ql[2], ql[3], sb + 16384 + a);
                }
#pragma unroll
                for (int p = 0; p < 4; ++p) {
                    const int row = p * 16 + b_sub * 8 + b_lrow;
                    const u32 a = swz(row, kt2 * 2 + b_lc);
                    u32 k0b[2], k1b[2], k0l[2], k1l[2];
                    ldsm4(k0b[0], k0b[1], k1b[0], k1b[1], stK + a);
                    ldsm4(k0l[0], k0l[1], k1l[0], k1l[1], stKl + a);
                    mma16816(S[2*p],   qh, k0b);
                    mma16816(S[2*p],   qh, k0l);
                    mma16816(S[2*p],   ql, k0b);
                    mma16816(S[2*p+1], qh, k1b);
                    mma16816(S[2*p+1], qh, k1l);
                    mma16816(S[2*p+1], ql, k1b);
                }
            }

            if (k0 + 63 > q0 + wm) {
                const int r0g = q0 + wm + (lane >> 2);
                const int cb  = k0 + (lane & 3) * 2;
#pragma unroll
                for (int n = 0; n < 8; ++n)
#pragma unroll
                    for (int e = 0; e < 2; ++e) {
                        const int col = cb + n * 8 + e;
                        if (col > r0g)     S[n][e]     = -1e30f;
                        if (col > r0g + 8) S[n][2 + e] = -1e30f;
                    }
            }

            float m0n = mrow[0], m1n = mrow[1];
#pragma unroll
            for (int n = 0; n < 8; ++n) {
                m0n = fmaxf(m0n, fmaxf(S[n][0], S[n][1]));
                m1n = fmaxf(m1n, fmaxf(S[n][2], S[n][3]));
            }
            m0n = fmaxf(m0n, __shfl_xor_sync(0xffffffffu, m0n, 1));
            m0n = fmaxf(m0n, __shfl_xor_sync(0xffffffffu, m0n, 2));
            m1n = fmaxf(m1n, __shfl_xor_sync(0xffffffffu, m1n, 1));
            m1n = fmaxf(m1n, __shfl_xor_sync(0xffffffffu, m1n, 2));

            const float sc0 = ex2(mrow[0] - m0n);
            const float sc1 = ex2(mrow[1] - m1n);
            mrow[0] = m0n; mrow[1] = m1n;

            float ps0 = 0.f, ps1 = 0.f;
#pragma unroll
            for (int n = 0; n < 8; ++n) {
                S[n][0] = ex2(S[n][0] - m0n); ps0 += S[n][0];
                S[n][1] = ex2(S[n][1] - m0n); ps0 += S[n][1];
                S[n][2] = ex2(S[n][2] - m1n); ps1 += S[n][2];
                S[n][3] = ex2(S[n][3] - m1n); ps1 += S[n][3];
            }
            ps0 += __shfl_xor_sync(0xffffffffu, ps0, 1);
            ps0 += __shfl_xor_sync(0xffffffffu, ps0, 2);
            ps1 += __shfl_xor_sync(0xffffffffu, ps1, 1);
            ps1 += __shfl_xor_sync(0xffffffffu, ps1, 2);
            lrow[0] = lrow[0] * sc0 + ps0;
            lrow[1] = lrow[1] * sc1 + ps1;
#pragma unroll
            for (int jn = 0; jn < 8; ++jn) {
                O[jn][0] *= sc0; O[jn][1] *= sc0;
                O[jn][2] *= sc1; O[jn][3] *= sc1;
            }

#pragma unroll
            for (int kt2 = 0; kt2 < 4; ++kt2) {
                u32 ph[4], pl[4];
                {
                    const int n0i = 2 * kt2, n1i = 2 * kt2 + 1;
                    const u32 u00 = __float_as_uint(S[n0i][0]);
                    const u32 u01 = __float_as_uint(S[n0i][1]);
                    const u32 u02 = __float_as_uint(S[n0i][2]);
                    const u32 u03 = __float_as_uint(S[n0i][3]);
                    const u32 u10 = __float_as_uint(S[n1i][0]);
                    const u32 u11 = __float_as_uint(S[n1i][1]);
                    const u32 u12 = __float_as_uint(S[n1i][2]);
                    const u32 u13 = __float_as_uint(S[n1i][3]);
                    ph[0] = prmt_hi2(u00, u01);
                    ph[1] = prmt_hi2(u02, u03);
                    ph[2] = prmt_hi2(u10, u11);
                    ph[3] = prmt_hi2(u12, u13);
                    pl[0] = pkbf(S[n0i][0] - __uint_as_float(u00 & 0xFFFF0000u),
                                 S[n0i][1] - __uint_as_float(u01 & 0xFFFF0000u));
                    pl[1] = pkbf(S[n0i][2] - __uint_as_float(u02 & 0xFFFF0000u),
                                 S[n0i][3] - __uint_as_float(u03 & 0xFFFF0000u));
                    pl[2] = pkbf(S[n1i][0] - __uint_as_float(u10 & 0xFFFF0000u),
                                 S[n1i][1] - __uint_as_float(u11 & 0xFFFF0000u));
                    pl[3] = pkbf(S[n1i][2] - __uint_as_float(u12 & 0xFFFF0000u),
                                 S[n1i][3] - __uint_as_float(u13 & 0xFFFF0000u));
                }
#pragma unroll
                for (int jp = 0; jp < 4; ++jp) {
                    const u32 a = swz(kt2 * 16 + a_lrow, jp * 2 + ((lane >> 4) & 1));
                    u32 v0[2], v1[2], vl0[2], vl1[2];
                    ldsm4t(v0[0], v0[1], v1[0], v1[1], stV + a);
                    ldsm4t(vl0[0], vl0[1], vl1[0], vl1[1], stVl + a);
                    mma16816(O[2*jp],   ph, v0);
                    mma16816(O[2*jp],   ph, vl0);
                    mma16816(O[2*jp],   pl, v0);
                    mma16816(O[2*jp+1], ph, v1);
                    mma16816(O[2*jp+1], ph, vl1);
                    mma16816(O[2*jp+1], pl, v1);
                }
            }
        }

        __syncthreads();
        if (kt + 2 < NCH) load_chunk(kt + 2, s);
    }

    // ---- epilogue: normalize, tf32-round, write g_atf [b,s,h*64+dd] fp32
    const int b = bh >> 4, h = bh & 15;
    const float inv0 = 1.0f / lrow[0];
    const float inv1 = 1.0f / lrow[1];
    const int r0g = q0 + wm + (lane >> 2);
    const int colb = h * 64 + (lane & 3) * 2;
#pragma unroll
    for (int jn = 0; jn < 8; ++jn) {
        const int col = colb + jn * 8;
        {
            float2 v;
            v.x = tf32r(O[jn][0] * inv0);
            v.y = tf32r(O[jn][1] * inv0);
            *(float2*)(g_atf + ((size_t)b * SQ + r0g) * DM + col) = v;
        }
        {
            float2 v;
            v.x = tf32r(O[jn][2] * inv1);
            v.y = tf32r(O[jn][3] * inv1);
            *(float2*)(g_atf + ((size_t)b * SQ + r0g + 8) * DM + col) = v;
        }
    }
}

// ============================================================================
extern "C" void kernel_launch(void* const* d_in, const int* in_sizes, int n_in,
                              void* d_out, int out_size)
{
    const float* x    = (const float*)d_in[0];
    const float* attw = (const float*)d_in[1];
    const float* attb = (const float*)d_in[2];
    const float* pw   = (const float*)d_in[3];
    const float* pb   = (const float*)d_in[4];
    float* out = (float*)d_out;

    const int MMA_SMEM  = 3 * 32768;          // 98304 -> 2 CTAs/SM
    const int ATTN_SMEM = 32768 + 2 * 32768;  // 98304 -> 2 CTAs/SM
    cudaFuncSetAttribute(mma_gemm<0>,
        cudaFuncAttributeMaxDynamicSharedMemorySize, MMA_SMEM);
    cudaFuncSetAttribute(mma_gemm<1>,
        cudaFuncAttributeMaxDynamicSharedMemorySize, MMA_SMEM);
    cudaFuncSetAttribute(attn_mma,
        cudaFuncAttributeMaxDynamicSharedMemorySize, ATTN_SMEM);

    conv_all<<<12288, 256>>>(x, attw, pw);

    mma_gemm<0><<<dim3(N3 / 128, BS / 128), 256, MMA_SMEM>>>(attb, nullptr);

    attn_mma<<<dim3(SQ / 128, BB * NH), 256, ATTN_SMEM>>>();

    mma_gemm<1><<<dim3(DM / 128, BS / 128), 256, MMA_SMEM>>>(pb, out);
}

// round 16
// speedup vs baseline: 2.0239x; 2.0239x over previous
#include <cuda_runtime.h>
#include <cuda_fp16.h>
#include <cstdint>

#define BB   4
#define SQ   2048
#define DM   1024
#define NH   16
#define HD   64
#define BS   (BB*SQ)      // 8192
#define N3   (3*DM)       // 3072

typedef unsigned long long u64;
typedef unsigned int u32;

// Q pre-scale: 1/sqrt(64) * log2(e)  (softmax done in base-2 domain)
#define QSCALE 0.1803368801111204f

// ---------------- scratch (device globals; no allocation allowed) -----------
__device__ __align__(16) __half g_q16[(size_t)BB*NH*SQ*HD];   // fp16, pre-scaled
__device__ __align__(16) __half g_k16[(size_t)BB*NH*SQ*HD];
__device__ __align__(16) __half g_v16[(size_t)BB*NH*SQ*HD];

__device__ __align__(16) __half g_x16[(size_t)BS*DM];   // x fp16
__device__ __align__(16) __half g_a16[(size_t)BS*DM];   // attn out fp16
__device__ __align__(16) __half g_wq16[(size_t)N3*DM];  // attw^T [3072][1024] fp16
__device__ __align__(16) __half g_wp16[(size_t)DM*DM];  // pw^T  [1024][1024] fp16

// ---------------- helpers -----------------------------------------------------
__device__ __forceinline__ void cp_async16(u32 smem, const void* g) {
    asm volatile("cp.async.cg.shared.global [%0], [%1], 16;" :: "r"(smem), "l"(g));
}
__device__ __forceinline__ void cp_commit()  { asm volatile("cp.async.commit_group;"); }
__device__ __forceinline__ void cp_wait0()   { asm volatile("cp.async.wait_group 0;"); }
__device__ __forceinline__ void cp_wait1()   { asm volatile("cp.async.wait_group 1;"); }
__device__ __forceinline__ u32 smem_u32(const void* p) {
    return (u32)__cvta_generic_to_shared(p);
}
__device__ __forceinline__ float ex2(float x) {
    float y; asm("ex2.approx.f32 %0, %1;" : "=f"(y) : "f"(x)); return y;
}
__device__ __forceinline__ void ldsm4(u32& r0, u32& r1, u32& r2, u32& r3, u32 a) {
    asm volatile("ldmatrix.sync.aligned.m8n8.x4.shared.b16 {%0,%1,%2,%3}, [%4];"
                 : "=r"(r0), "=r"(r1), "=r"(r2), "=r"(r3) : "r"(a));
}
__device__ __forceinline__ void ldsm4t(u32& r0, u32& r1, u32& r2, u32& r3, u32 a) {
    asm volatile("ldmatrix.sync.aligned.m8n8.x4.trans.shared.b16 {%0,%1,%2,%3}, [%4];"
                 : "=r"(r0), "=r"(r1), "=r"(r2), "=r"(r3) : "r"(a));
}
__device__ __forceinline__ void mma_f16(float* d, const u32* a, const u32* b) {
    asm volatile(
        "mma.sync.aligned.m16n8k16.row.col.f32.f16.f16.f32 "
        "{%0,%1,%2,%3}, {%4,%5,%6,%7}, {%8,%9}, {%0,%1,%2,%3};"
        : "+f"(d[0]), "+f"(d[1]), "+f"(d[2]), "+f"(d[3])
        : "r"(a[0]), "r"(a[1]), "r"(a[2]), "r"(a[3]), "r"(b[0]), "r"(b[1]));
}
__device__ __forceinline__ u32 pkh(float a, float b) {
    __half2 h = __floats2half2_rn(a, b);
    return *(u32*)&h;
}
// swizzled byte offset in a [rows x 128B] tile (SW128 style)
__device__ __forceinline__ u32 swz(int r, int c) {
    return (u32)(r * 128 + ((c ^ (r & 7)) * 16));
}

// ============================================================================
// Merged prep: x -> fp16, both weight transposes -> fp16 [n][k]
// blocks [0,8192): x   [8192,11264): attw^T   [11264,12288): pw^T
// ============================================================================
__global__ __launch_bounds__(256) void conv_all(const float* __restrict__ x,
                                                const float* __restrict__ attw,
                                                const float* __restrict__ pw)
{
    __shared__ float t[32][33];
    const int bid = blockIdx.x;
    if (bid < 8192) {
        const int i = bid * 256 + threadIdx.x;      // n4 = 2097152
        float4 v = ((const float4*)x)[i];
        uint2 o;
        o.x = pkh(v.x, v.y);
        o.y = pkh(v.z, v.w);
        ((uint2*)g_x16)[i] = o;
        return;
    }
    const float* w; __half* dst; int K, N, n0, k0;
    if (bid < 8192 + 3072) {
        const int tb = bid - 8192;
        w = attw; dst = g_wq16; K = DM; N = N3;
        n0 = (tb % 96) * 32; k0 = (tb / 96) * 32;
    } else {
        const int tb = bid - 11264;
        w = pw; dst = g_wp16; K = DM; N = DM;
        n0 = (tb % 32) * 32; k0 = (tb / 32) * 32;
    }
    const int xl = threadIdx.x & 31, y = (threadIdx.x >> 5) * 4;
#pragma unroll
    for (int r = 0; r < 4; ++r)
        t[y + r][xl] = w[(size_t)(k0 + y + r) * N + n0 + xl];
    __syncthreads();
#pragma unroll
    for (int r = 0; r < 4; ++r) {
        const int n = n0 + y + r, kk = k0 + xl;
        dst[(size_t)n * K + kk] = __float2half(t[xl][y + r]);
    }
}

// ============================================================================
// fp16 single-pass GEMM via mma.sync.m16n8k16. 128x128 CTA, 8 warps (64x32),
// BK=64 (4 k16 steps), 3 stages x 32KB = 96KB -> 2 CTAs/SM, 1 sync/chunk.
// A tile 128x64 fp16 (128B rows, SW128), B tile 128x64 fp16.
// MODE 0: qkv -> fp16 scatter (Q scaled).  MODE 1: proj -> fp32 out + bias.
// ============================================================================
template<int MODE>
__global__ __launch_bounds__(256, 2) void mma_gemm(const float* __restrict__ bias,
                                                   float* __restrict__ outp)
{
    extern __shared__ char smem[];
    const u32 sb = smem_u32(smem);
    const int tx = threadIdx.x, wid = tx >> 5, lane = tx & 31;
    const int m0 = blockIdx.y * 128, n0 = blockIdx.x * 128;
    const int K = DM;
    const int NCH = K / 64;                 // 16 chunks

    const __half* Ag = MODE ? g_a16  : g_x16;
    const __half* Bg = MODE ? g_wp16 : g_wq16;

    const int wm = (wid & 1) * 64;
    const int wn = (wid >> 1) * 32;

    auto load_chunk = [&](int ci, int stage) {
        const int k0 = ci * 64;
#pragma unroll
        for (int t = 0; t < 2; ++t) {
            const __half* src = t ? Bg : Ag;
            const int rbase   = t ? n0 : m0;
            const u32 tb = sb + (u32)(stage * 32768 + t * 16384);
#pragma unroll
            for (int u = 0; u < 4; ++u) {
                const int id = tx + 256 * u;
                const int r = id >> 3, c = id & 7;
                cp_async16(tb + swz(r, c),
                           src + (size_t)(rbase + r) * K + k0 + c * 8);
            }
        }
        cp_commit();
    };

    float acc[4][4][4];
#pragma unroll
    for (int mt = 0; mt < 4; ++mt)
#pragma unroll
        for (int nt = 0; nt < 4; ++nt)
#pragma unroll
            for (int e = 0; e < 4; ++e) acc[mt][nt][e] = 0.f;

    load_chunk(0, 0);
    load_chunk(1, 1);

    const int a_lrow = lane & 15;
    const int a_lc   = lane >> 4;
    const int b_lrow = lane & 7;
    const int b_lc   = (lane >> 3) & 1;
    const int b_sub  = (lane >> 4) & 1;

    for (int i = 0; i < NCH; ++i) {
        const int s = i % 3;
        if (i + 1 < NCH) cp_wait1(); else cp_wait0();
        __syncthreads();
        if (i + 2 < NCH) load_chunk(i + 2, (i + 2) % 3);

        const u32 tA = sb + (u32)(s * 32768);
        const u32 tB = tA + 16384;

#pragma unroll
        for (int ks = 0; ks < 4; ++ks) {
            u32 af[4][4];
#pragma unroll
            for (int mt = 0; mt < 4; ++mt) {
                const int row = wm + mt * 16 + a_lrow;
                ldsm4(af[mt][0], af[mt][1], af[mt][2], af[mt][3],
                      tA + swz(row, ks * 2 + a_lc));
            }
            u32 bfr[4][2];
#pragma unroll
            for (int p = 0; p < 2; ++p) {
                const int row = wn + p * 16 + b_sub * 8 + b_lrow;
                const int c   = ks * 2 + b_lc;
                ldsm4(bfr[2*p][0], bfr[2*p][1], bfr[2*p+1][0], bfr[2*p+1][1],
                      tB + swz(row, c));
            }
#pragma unroll
            for (int mt = 0; mt < 4; ++mt)
#pragma unroll
                for (int nt = 0; nt < 4; ++nt)
                    mma_f16(acc[mt][nt], af[mt], bfr[nt]);
        }
    }

    const int r_in  = lane >> 2;
    const int cpair = (lane & 3) * 2;

    if (MODE == 0) {
        const int seg = n0 >> 10;
        __half* d16 = (seg == 0) ? g_q16 : (seg == 1) ? g_k16 : g_v16;
        const float qs = (seg == 0) ? QSCALE : 1.0f;
#pragma unroll
        for (int mt = 0; mt < 4; ++mt)
#pragma unroll
            for (int nt = 0; nt < 4; ++nt)
#pragma unroll
                for (int hh = 0; hh < 2; ++hh) {
                    const int m = m0 + wm + mt * 16 + r_in + hh * 8;
                    const int n = n0 + wn + nt * 8 + cpair;
                    const int b  = m >> 11;
                    const int sI = m & 2047;
                    const int nn = n & 1023;
                    const int h  = nn >> 6, dd = nn & 63;
                    const float vx = (acc[mt][nt][hh*2+0] + bias[n]) * qs;
                    const float vy = (acc[mt][nt][hh*2+1] + bias[n+1]) * qs;
                    const size_t idx = ((((size_t)b * NH + h) * SQ + sI) << 6) + dd;
                    *(u32*)(d16 + idx) = pkh(vx, vy);
                }
    } else {
#pragma unroll
        for (int mt = 0; mt < 4; ++mt)
#pragma unroll
            for (int nt = 0; nt < 4; ++nt)
#pragma unroll
                for (int hh = 0; hh < 2; ++hh) {
                    const int m = m0 + wm + mt * 16 + r_in + hh * 8;
                    const int n = n0 + wn + nt * 8 + cpair;
                    float2 v;
                    v.x = acc[mt][nt][hh * 2 + 0] + bias[n];
                    v.y = acc[mt][nt][hh * 2 + 1] + bias[n + 1];
                    *(float2*)(outp + (size_t)m * DM + n) = v;
                }
    }
}

// ============================================================================
// fp16 tensor-core flash attention. CTA = 128 q-rows x one (b,h). 8 warps,
// 16 rows each. K-chunks of 64 keys, 2 stages, 48KB smem -> 2 CTAs/SM.
// LPT long-tiles-first. smem: Q 16K | 2 stages x {K 8K, V 8K}.
// Epilogue writes fp16 output into g_a16 (proj input).
// ============================================================================
__global__ __launch_bounds__(256, 2) void attn_mma()
{
    extern __shared__ char smem[];
    const u32 sb = smem_u32(smem);
    const int tx = threadIdx.x, wid = tx >> 5, lane = tx & 31;
    const int qt = (int)gridDim.x - 1 - (int)blockIdx.x;   // LPT
    const int bh = blockIdx.y;
    const int q0 = qt * 128;
    const int wm = wid * 16;
    const size_t base = (size_t)bh * SQ * HD;

    const __half* Qg = g_q16 + base;
    const __half* Kg = g_k16 + base;
    const __half* Vg = g_v16 + base;

    // Q: 128 rows x 64 fp16 (128B rows)
#pragma unroll
    for (int u = 0; u < 4; ++u) {
        const int id = tx + 256 * u;
        const int r = id >> 3, c = id & 7;
        cp_async16(sb + swz(r, c), Qg + (size_t)(q0 + r) * HD + c * 8);
    }
    auto load_chunk = [&](int kt, int s) {
        const int k0 = kt * 64;
        const u32 st = sb + 16384 + (u32)s * 16384;
#pragma unroll
        for (int u = 0; u < 2; ++u) {
            const int id = tx + 256 * u;
            const int r = id >> 3, c = id & 7;
            cp_async16(st + swz(r, c),        Kg + (size_t)(k0 + r) * HD + c * 8);
            cp_async16(st + 8192 + swz(r, c), Vg + (size_t)(k0 + r) * HD + c * 8);
        }
        cp_commit();
    };
    load_chunk(0, 0);                 // group includes Q loads
    const int NCH = 2 * qt + 2;       // >= 2
    load_chunk(1, 1);

    float O[8][4];
#pragma unroll
    for (int jn = 0; jn < 8; ++jn)
#pragma unroll
        for (int e = 0; e < 4; ++e) O[jn][e] = 0.f;
    float mrow[2] = {-1e30f, -1e30f};
    float lrow[2] = {0.f, 0.f};

    const int a_lrow = lane & 15;
    const int a_lc   = lane >> 4;
    const int b_lrow = lane & 7;
    const int b_lc   = (lane >> 3) & 1;
    const int b_sub  = (lane >> 4) & 1;

    for (int kt = 0; kt < NCH; ++kt) {
        const int s = kt & 1;
        const int k0 = kt * 64;
        if (kt + 1 < NCH) cp_wait1(); else cp_wait0();
        __syncthreads();

        const bool active = (k0 <= q0 + wm + 15);
        if (active) {
            const u32 stK = sb + 16384 + (u32)s * 16384;
            const u32 stV = stK + 8192;

            float S[8][4];
#pragma unroll
            for (int n = 0; n < 8; ++n)
#pragma unroll
                for (int e = 0; e < 4; ++e) S[n][e] = 0.f;

            // ---- QK: 4 k16-steps x 8 n8-tiles, single fp16
#pragma unroll
            for (int kt2 = 0; kt2 < 4; ++kt2) {
                u32 qf[4];
                ldsm4(qf[0], qf[1], qf[2], qf[3],
                      sb + swz(wm + a_lrow, kt2 * 2 + a_lc));
#pragma unroll
                for (int p = 0; p < 4; ++p) {
                    const int row = p * 16 + b_sub * 8 + b_lrow;
                    u32 k0b[2], k1b[2];
                    ldsm4(k0b[0], k0b[1], k1b[0], k1b[1],
                          stK + swz(row, kt2 * 2 + b_lc));
                    mma_f16(S[2*p],   qf, k0b);
                    mma_f16(S[2*p+1], qf, k1b);
                }
            }

            if (k0 + 63 > q0 + wm) {
                const int r0g = q0 + wm + (lane >> 2);
                const int cb  = k0 + (lane & 3) * 2;
#pragma unroll
                for (int n = 0; n < 8; ++n)
#pragma unroll
                    for (int e = 0; e < 2; ++e) {
                        const int col = cb + n * 8 + e;
                        if (col > r0g)     S[n][e]     = -1e30f;
                        if (col > r0g + 8) S[n][2 + e] = -1e30f;
                    }
            }

            // ---- online softmax (base-2)
            float m0n = mrow[0], m1n = mrow[1];
#pragma unroll
            for (int n = 0; n < 8; ++n) {
                m0n = fmaxf(m0n, fmaxf(S[n][0], S[n][1]));
                m1n = fmaxf(m1n, fmaxf(S[n][2], S[n][3]));
            }
            m0n = fmaxf(m0n, __shfl_xor_sync(0xffffffffu, m0n, 1));
            m0n = fmaxf(m0n, __shfl_xor_sync(0xffffffffu, m0n, 2));
            m1n = fmaxf(m1n, __shfl_xor_sync(0xffffffffu, m1n, 1));
            m1n = fmaxf(m1n, __shfl_xor_sync(0xffffffffu, m1n, 2));

            const float sc0 = ex2(mrow[0] - m0n);
            const float sc1 = ex2(mrow[1] - m1n);
            mrow[0] = m0n; mrow[1] = m1n;

            float ps0 = 0.f, ps1 = 0.f;
#pragma unroll
            for (int n = 0; n < 8; ++n) {
                S[n][0] = ex2(S[n][0] - m0n); ps0 += S[n][0];
                S[n][1] = ex2(S[n][1] - m0n); ps0 += S[n][1];
                S[n][2] = ex2(S[n][2] - m1n); ps1 += S[n][2];
                S[n][3] = ex2(S[n][3] - m1n); ps1 += S[n][3];
            }
            ps0 += __shfl_xor_sync(0xffffffffu, ps0, 1);
            ps0 += __shfl_xor_sync(0xffffffffu, ps0, 2);
            ps1 += __shfl_xor_sync(0xffffffffu, ps1, 1);
            ps1 += __shfl_xor_sync(0xffffffffu, ps1, 2);
            lrow[0] = lrow[0] * sc0 + ps0;
            lrow[1] = lrow[1] * sc1 + ps1;
#pragma unroll
            for (int jn = 0; jn < 8; ++jn) {
                O[jn][0] *= sc0; O[jn][1] *= sc0;
                O[jn][2] *= sc1; O[jn][3] *= sc1;
            }

            // ---- P @ V (single fp16): P frags packed from S registers
#pragma unroll
            for (int kt2 = 0; kt2 < 4; ++kt2) {
                u32 ph[4];
                {
                    const int n0i = 2 * kt2, n1i = 2 * kt2 + 1;
                    ph[0] = pkh(S[n0i][0], S[n0i][1]);
                    ph[1] = pkh(S[n0i][2], S[n0i][3]);
                    ph[2] = pkh(S[n1i][0], S[n1i][1]);
                    ph[3] = pkh(S[n1i][2], S[n1i][3]);
                }
#pragma unroll
                for (int jp = 0; jp < 4; ++jp) {
                    const u32 a = swz(kt2 * 16 + a_lrow, jp * 2 + a_lc);
                    u32 v0[2], v1[2];
                    ldsm4t(v0[0], v0[1], v1[0], v1[1], stV + a);
                    mma_f16(O[2*jp],   ph, v0);
                    mma_f16(O[2*jp+1], ph, v1);
                }
            }
        }

        __syncthreads();
        if (kt + 2 < NCH) load_chunk(kt + 2, s);
    }

    // ---- epilogue: normalize, write fp16 g_a16 [b,s,h*64+dd]
    const int b = bh >> 4, h = bh & 15;
    const float inv0 = 1.0f / lrow[0];
    const float inv1 = 1.0f / lrow[1];
    const int r0g = q0 + wm + (lane >> 2);
    const int colb = h * 64 + (lane & 3) * 2;
#pragma unroll
    for (int jn = 0; jn < 8; ++jn) {
        const int col = colb + jn * 8;
        *(u32*)(g_a16 + ((size_t)b * SQ + r0g) * DM + col) =
            pkh(O[jn][0] * inv0, O[jn][1] * inv0);
        *(u32*)(g_a16 + ((size_t)b * SQ + r0g + 8) * DM + col) =
            pkh(O[jn][2] * inv1, O[jn][3] * inv1);
    }
}

// ============================================================================
extern "C" void kernel_launch(void* const* d_in, const int* in_sizes, int n_in,
                              void* d_out, int out_size)
{
    const float* x    = (const float*)d_in[0];
    const float* attw = (const float*)d_in[1];
    const float* attb = (const float*)d_in[2];
    const float* pw   = (const float*)d_in[3];
    const float* pb   = (const float*)d_in[4];
    float* out = (float*)d_out;

    const int MMA_SMEM  = 3 * 32768;          // 98304 -> 2 CTAs/SM
    const int ATTN_SMEM = 16384 + 2 * 16384;  // 49152 -> 2 CTAs/SM
    cudaFuncSetAttribute(mma_gemm<0>,
        cudaFuncAttributeMaxDynamicSharedMemorySize, MMA_SMEM);
    cudaFuncSetAttribute(mma_gemm<1>,
        cudaFuncAttributeMaxDynamicSharedMemorySize, MMA_SMEM);
    cudaFuncSetAttribute(attn_mma,
        cudaFuncAttributeMaxDynamicSharedMemorySize, ATTN_SMEM);

    conv_all<<<12288, 256>>>(x, attw, pw);

    mma_gemm<0><<<dim3(N3 / 128, BS / 128), 256, MMA_SMEM>>>(attb, nullptr);

    attn_mma<<<dim3(SQ / 128, BB * NH), 256, ATTN_SMEM>>>();

    mma_gemm<1><<<dim3(DM / 128, BS / 128), 256, MMA_SMEM>>>(pb, out);
}